// round 15
// baseline (speedup 1.0000x reference)
#include <cuda_runtime.h>
#include <cuda_fp16.h>

#define NN   100000
#define EE   1600000
#define GG   100
#define HH   128
#define OUTF 10
#define CAP  128
#define PITCH 136   // smem row pitch in halves (conflict-free for ldmatrix)

// ---------- device scratch (static zero-init; self-cleaning across replays) ----------
__device__ __half g_hs1[(size_t)NN * HH];  // dis * relu(layer1)  (pre-scaled msgs)
__device__ __half g_ts[(size_t)NN * HH];   // dis * T  (gemm2 input)
__device__ __half g_W2h[HH * HH];          // W2 in fp16 (built by k_pre)
__device__ int    g_pad[(size_t)NN * CAP]; // scaled src indices (src*32)
__device__ int    g_cur[NN];               // in-degree / cursor (zeroed by k_agg2)
__device__ float4 g_xs[NN];                // (dis*x0, dis*x1, dis*x2, dis)
__device__ float  g_dis[NN];
__device__ float  g_pooled[GG * HH];       // zeroed by last gemm2pool block
__device__ float  g_gcnt[GG];
__device__ unsigned g_ticket;              // last-block election (self-reset)

__device__ __forceinline__ unsigned smem_u32(const void* p) {
    return (unsigned)__cvta_generic_to_shared(p);
}
__device__ __forceinline__ uint2 pack_h4(float4 o) {
    __half2 lo = __floats2half2_rn(o.x, o.y);
    __half2 hi = __floats2half2_rn(o.z, o.w);
    uint2 r; r.x = *(unsigned*)&lo; r.y = *(unsigned*)&hi; return r;
}

// ---------- mma / ldmatrix ----------
__device__ __forceinline__ void mma16816(float d[4], const unsigned a[4],
                                         const unsigned b[2], const float c[4]) {
    asm volatile(
        "mma.sync.aligned.m16n8k16.row.col.f32.f16.f16.f32 "
        "{%0,%1,%2,%3}, {%4,%5,%6,%7}, {%8,%9}, {%10,%11,%12,%13};\n"
        : "=f"(d[0]), "=f"(d[1]), "=f"(d[2]), "=f"(d[3])
        : "r"(a[0]), "r"(a[1]), "r"(a[2]), "r"(a[3]),
          "r"(b[0]), "r"(b[1]),
          "f"(c[0]), "f"(c[1]), "f"(c[2]), "f"(c[3]));
}
__device__ __forceinline__ void ldsm_x4(unsigned r[4], unsigned addr) {
    asm volatile("ldmatrix.sync.aligned.m8n8.x4.shared.b16 {%0,%1,%2,%3}, [%4];\n"
        : "=r"(r[0]), "=r"(r[1]), "=r"(r[2]), "=r"(r[3]) : "r"(addr));
}
__device__ __forceinline__ void ldsm_x4_t(unsigned r[4], unsigned addr) {
    asm volatile("ldmatrix.sync.aligned.m8n8.x4.trans.shared.b16 {%0,%1,%2,%3}, [%4];\n"
        : "=r"(r[0]), "=r"(r[1]), "=r"(r[2]), "=r"(r[3]) : "r"(addr));
}

// ---------- fp16 feature-space gather (lane owns 4 features = uint2) ----------
__device__ __forceinline__ void hacc2(__half2& h0, __half2& h1, uint2 v) {
    h0 = __hadd2(h0, *(__half2*)&v.x);
    h1 = __hadd2(h1, *(__half2*)&v.y);
}

__device__ __forceinline__ float4 gather_sum_h(const __half* __restrict__ buf,
                                               int n, int lane) {
    int cnt = g_cur[n]; if (cnt > CAP) cnt = CAP;
    const int* lst = g_pad + (size_t)n * CAP;
    const uint2* A = (const uint2*)buf;           // row = 32 uint2
    float4 fa = {0.f, 0.f, 0.f, 0.f};
    const __half2 z = __float2half2_rn(0.f);
    __half2 h0 = z, h1 = z;

    int k = 0, sf = 0;
    for (; k + 8 <= cnt; k += 8) {
        int4 a = *(const int4*)&lst[k];
        int4 b = *(const int4*)&lst[k + 4];
        uint2 v0 = __ldg(&A[a.x + lane]);
        uint2 v1 = __ldg(&A[a.y + lane]);
        uint2 v2 = __ldg(&A[a.z + lane]);
        uint2 v3 = __ldg(&A[a.w + lane]);
        uint2 v4 = __ldg(&A[b.x + lane]);
        uint2 v5 = __ldg(&A[b.y + lane]);
        uint2 v6 = __ldg(&A[b.z + lane]);
        uint2 v7 = __ldg(&A[b.w + lane]);
        hacc2(h0, h1, v0); hacc2(h0, h1, v1);
        hacc2(h0, h1, v2); hacc2(h0, h1, v3);
        hacc2(h0, h1, v4); hacc2(h0, h1, v5);
        hacc2(h0, h1, v6); hacc2(h0, h1, v7);
        if (++sf == 2) {                          // flush every 16 edges
            float2 f0 = __half22float2(h0), f1 = __half22float2(h1);
            fa.x += f0.x; fa.y += f0.y; fa.z += f1.x; fa.w += f1.y;
            h0 = z; h1 = z; sf = 0;
        }
    }
    if (k + 4 <= cnt) {
        int4 a = *(const int4*)&lst[k];
        uint2 v0 = __ldg(&A[a.x + lane]);
        uint2 v1 = __ldg(&A[a.y + lane]);
        uint2 v2 = __ldg(&A[a.z + lane]);
        uint2 v3 = __ldg(&A[a.w + lane]);
        hacc2(h0, h1, v0); hacc2(h0, h1, v1);
        hacc2(h0, h1, v2); hacc2(h0, h1, v3);
        k += 4;
    }
    for (; k < cnt; k++)
        hacc2(h0, h1, __ldg(&A[__ldg(&lst[k]) + lane]));
    hacc2(h0, h1, A[n * 32 + lane]);              // self loop (pre-scaled row)
    float2 f0 = __half22float2(h0), f1 = __half22float2(h1);
    fa.x += f0.x; fa.y += f0.y; fa.z += f1.x; fa.w += f1.y;
    return fa;
}

// ---------- kernels ----------
__global__ void k_fill(const int* __restrict__ src, const int* __restrict__ dst) {
    int i = blockIdx.x * blockDim.x + threadIdx.x;
    if (i >= EE / 4) return;
    int4 d4 = __ldg(&((const int4*)dst)[i]);
    int4 s4 = __ldg(&((const int4*)src)[i]);
    int p0 = atomicAdd(&g_cur[d4.x], 1); if (p0 < CAP) g_pad[d4.x * CAP + p0] = s4.x * 32;
    int p1 = atomicAdd(&g_cur[d4.y], 1); if (p1 < CAP) g_pad[d4.y * CAP + p1] = s4.y * 32;
    int p2 = atomicAdd(&g_cur[d4.z], 1); if (p2 < CAP) g_pad[d4.z * CAP + p2] = s4.z * 32;
    int p3 = atomicAdd(&g_cur[d4.w], 1); if (p3 < CAP) g_pad[d4.w * CAP + p3] = s4.w * 32;
}

// dis + pre-scaled x; also converts W2 -> fp16 (threads 0..16383)
__global__ void k_pre(const float* __restrict__ x, const float* __restrict__ W2) {
    int i = blockIdx.x * blockDim.x + threadIdx.x;
    if (i < HH * HH) g_W2h[i] = __float2half_rn(__ldg(&W2[i]));
    if (i >= NN) return;
    float dis = rsqrtf((float)(g_cur[i] + 1));
    g_dis[i] = dis;
    float x0 = __ldg(&x[i * 3 + 0]);
    float x1 = __ldg(&x[i * 3 + 1]);
    float x2 = __ldg(&x[i * 3 + 2]);
    g_xs[i] = make_float4(dis * x0, dis * x1, dis * x2, dis);
}

// Layer 1 fused: x-space gather (thread per node, MLP-8) + W1 gemm
__global__ void __launch_bounds__(256) k_layer1(const float* __restrict__ W1,
                                                const float* __restrict__ b1) {
    __shared__ float4 sS[256];
    int tid = threadIdx.x;
    int n = blockIdx.x * 256 + tid;

    if (n < NN) {
        int cnt = g_cur[n]; if (cnt > CAP) cnt = CAP;
        const int* lst = g_pad + (size_t)n * CAP;
        float4 self = g_xs[n];
        float dis = self.w;
        float sx = self.x, sy = self.y, sz = self.z;
        int k = 0;
        for (; k + 8 <= cnt; k += 8) {
            int4 a = *(const int4*)&lst[k];
            int4 b = *(const int4*)&lst[k + 4];
            float4 v0 = __ldg(&g_xs[a.x >> 5]);
            float4 v1 = __ldg(&g_xs[a.y >> 5]);
            float4 v2 = __ldg(&g_xs[a.z >> 5]);
            float4 v3 = __ldg(&g_xs[a.w >> 5]);
            float4 v4 = __ldg(&g_xs[b.x >> 5]);
            float4 v5 = __ldg(&g_xs[b.y >> 5]);
            float4 v6 = __ldg(&g_xs[b.z >> 5]);
            float4 v7 = __ldg(&g_xs[b.w >> 5]);
            sx += v0.x + v1.x + v2.x + v3.x + v4.x + v5.x + v6.x + v7.x;
            sy += v0.y + v1.y + v2.y + v3.y + v4.y + v5.y + v6.y + v7.y;
            sz += v0.z + v1.z + v2.z + v3.z + v4.z + v5.z + v6.z + v7.z;
        }
        if (k + 4 <= cnt) {
            int4 a = *(const int4*)&lst[k];
            float4 v0 = __ldg(&g_xs[a.x >> 5]);
            float4 v1 = __ldg(&g_xs[a.y >> 5]);
            float4 v2 = __ldg(&g_xs[a.z >> 5]);
            float4 v3 = __ldg(&g_xs[a.w >> 5]);
            sx += v0.x + v1.x + v2.x + v3.x;
            sy += v0.y + v1.y + v2.y + v3.y;
            sz += v0.z + v1.z + v2.z + v3.z;
            k += 4;
        }
        for (; k < cnt; k++) {
            float4 v = __ldg(&g_xs[__ldg(&lst[k]) >> 5]);
            sx += v.x; sy += v.y; sz += v.z;
        }
        sS[tid] = make_float4(sx, sy, sz, dis);
    }
    __syncthreads();

    int w = tid >> 5, lane = tid & 31;
    const float4* W = ((const float4*)W1) + lane;
    float4 w0 = W[0], w1 = W[32], w2 = W[64];
    float4 bb = ((const float4*)b1)[lane];
    int base = blockIdx.x * 256 + w * 32;
#pragma unroll 4
    for (int it = 0; it < 32; it++) {
        int node = base + it;
        if (node >= NN) break;
        float4 s = sS[w * 32 + it];
        float dis = s.w;
        float4 o;
        float tx = fmaf(dis, fmaf(s.x, w0.x, fmaf(s.y, w1.x, s.z * w2.x)), bb.x);
        float ty = fmaf(dis, fmaf(s.x, w0.y, fmaf(s.y, w1.y, s.z * w2.y)), bb.y);
        float tz = fmaf(dis, fmaf(s.x, w0.z, fmaf(s.y, w1.z, s.z * w2.z)), bb.z);
        float tw = fmaf(dis, fmaf(s.x, w0.w, fmaf(s.y, w1.w, s.z * w2.w)), bb.w);
        o.x = fmaxf(tx, 0.f) * dis;
        o.y = fmaxf(ty, 0.f) * dis;
        o.z = fmaxf(tz, 0.f) * dis;
        o.w = fmaxf(tw, 0.f) * dis;
        ((uint2*)(g_hs1 + (size_t)node * HH))[lane] = pack_h4(o);
    }
}

// Layer-2 gather: ts = dis_i * (hs1_i + sum_j hs1_j). Warp per node (high occ).
__global__ void __launch_bounds__(256) k_agg2() {
    int gid = blockIdx.x * blockDim.x + threadIdx.x;
    int n = gid >> 5, lane = gid & 31;
    float4 a = gather_sum_h(g_hs1, n, lane);
    if (lane == 0) g_cur[n] = 0;               // self-clean for next launch
    float dis = g_dis[n];
    float4 o;
    o.x = a.x * dis; o.y = a.y * dis; o.z = a.z * dis; o.w = a.w * dis;
    ((uint2*)(g_ts + (size_t)n * HH))[lane] = pack_h4(o);
}

// HMMA ts@W2 + bias + relu + mean-pool + (last block) final head.
__global__ void __launch_bounds__(256) k_gemm2pool(const float* __restrict__ b2,
                                                   const int* __restrict__ batch,
                                                   const float* __restrict__ Wl,
                                                   const float* __restrict__ bl,
                                                   float* __restrict__ out) {
    extern __shared__ __half sh[];
    __half* sh_h = sh;                  // [128][PITCH]
    __half* sh_w = sh + 128 * PITCH;    // [128][PITCH]
    __shared__ float sb2[HH];
    __shared__ int sbatch[128];
    __shared__ bool slast;
    int t = threadIdx.x;
    int nb0 = blockIdx.x * 128;

    for (int i = t; i < 128 * 16; i += 256) {
        int r = i >> 4, c8 = (i & 15) * 8;
        int node = nb0 + r; if (node >= NN) node = NN - 1;
        *(uint4*)&sh_h[r * PITCH + c8] = *(const uint4*)&g_ts[(size_t)node * HH + c8];
        *(uint4*)&sh_w[r * PITCH + c8] = *(const uint4*)&g_W2h[r * HH + c8];
    }
    if (t < HH) sb2[t] = __ldg(&b2[t]);
    if (t < 128) {
        int node = nb0 + t;
        sbatch[t] = (node < NN) ? __ldg(&batch[node]) : -1;
    }
    __syncthreads();

    int w = t >> 5, lane = t & 31;
    int r0 = w * 16;
    float acc[16][4];
#pragma unroll
    for (int j = 0; j < 16; j++)
#pragma unroll
        for (int q = 0; q < 4; q++) acc[j][q] = 0.f;

    int a_row = r0 + (lane & 15);
    int a_col = (lane >> 4) * 8;

    for (int kc = 0; kc < 8; kc++) {
        int k0 = kc * 16;
        unsigned a[4];
        ldsm_x4(a, smem_u32(&sh_h[a_row * PITCH + k0 + a_col]));
        // B frags: x4.trans loads TWO column-pairs at once (lanes 16-31 -> next j)
        unsigned b_base = smem_u32(&sh_w[(k0 + (lane & 15)) * PITCH + (lane >> 4) * 8]);
#pragma unroll
        for (int j = 0; j < 16; j += 2) {
            unsigned b4[4];
            ldsm_x4_t(b4, b_base + j * 16);     // j*8 halves = j*16 bytes
            mma16816(acc[j],     a, b4,     acc[j]);
            mma16816(acc[j + 1], a, b4 + 2, acc[j + 1]);
        }
    }
    __syncthreads();                    // reuse smem as fp32 staging

    float* stg = (float*)sh;            // [128][128] fp32 = 64KB
    int lrow = lane >> 2;
    int lcol = (lane & 3) * 2;
    int row0 = r0 + lrow, row1 = row0 + 8;
#pragma unroll
    for (int j = 0; j < 16; j++) {
        int col = j * 8 + lcol;
        stg[row0 * 128 + col]     = fmaxf(acc[j][0] + sb2[col], 0.f);
        stg[row0 * 128 + col + 1] = fmaxf(acc[j][1] + sb2[col + 1], 0.f);
        stg[row1 * 128 + col]     = fmaxf(acc[j][2] + sb2[col], 0.f);
        stg[row1 * 128 + col + 1] = fmaxf(acc[j][3] + sb2[col + 1], 0.f);
    }
    __syncthreads();

    if (t < HH) {
        int g0 = sbatch[0];
        float s = 0.f;
        for (int r = 0; r < 128; r++) {
            int g = sbatch[r];
            if (g < 0) continue;
            float v = stg[r * 128 + t];
            if (g == g0) s += v;
            else atomicAdd(&g_pooled[g * HH + t], v);
        }
        atomicAdd(&g_pooled[g0 * HH + t], s);
    } else if (t == HH) {
        int g0 = sbatch[0];
        float c0 = 0.f;
        for (int r = 0; r < 128; r++) {
            int g = sbatch[r];
            if (g < 0) continue;
            if (g == g0) c0 += 1.f;
            else atomicAdd(&g_gcnt[g], 1.f);
        }
        atomicAdd(&g_gcnt[g0], c0);
    }

    // ---- last-block final head (replaces k_final launch) ----
    __threadfence();
    __syncthreads();
    if (t == 0) {
        unsigned tk = atomicAdd(&g_ticket, 1u);
        slast = (tk == gridDim.x - 1);
    }
    __syncthreads();
    if (!slast) return;

    for (int idx = t; idx < GG * OUTF; idx += 256) {
        int g = idx / OUTF, o = idx % OUTF;
        float inv = 1.f / fmaxf(g_gcnt[g], 1.f);
        float s = 0.f;
#pragma unroll 8
        for (int k = 0; k < HH; k++)
            s = fmaf(g_pooled[g * HH + k], __ldg(&Wl[k * OUTF + o]), s);
        out[idx] = fmaf(s, inv, __ldg(&bl[o]));
    }
    __syncthreads();
    for (int i = t; i < GG * HH; i += 256) g_pooled[i] = 0.f;
    if (t < GG) g_gcnt[t] = 0.f;
    if (t == 0) g_ticket = 0u;
}

// ---------- launch ----------
extern "C" void kernel_launch(void* const* d_in, const int* in_sizes, int n_in,
                              void* d_out, int out_size) {
    const float* x     = (const float*)d_in[0];
    const int*   ei    = (const int*)d_in[1];
    const int*   src   = ei;
    const int*   dst   = ei + EE;
    const int*   batch = (const int*)d_in[2];
    const float* W1    = (const float*)d_in[3];
    const float* b1    = (const float*)d_in[4];
    const float* W2    = (const float*)d_in[5];
    const float* b2    = (const float*)d_in[6];
    const float* Wl    = (const float*)d_in[7];
    const float* bl    = (const float*)d_in[8];
    float* out = (float*)d_out;

    const int SMEM_MMA = 2 * 128 * PITCH * (int)sizeof(__half);   // 69632
    cudaFuncSetAttribute(k_gemm2pool,
                         cudaFuncAttributeMaxDynamicSharedMemorySize, SMEM_MMA);

    const int T = 256;
    int bE = (EE / 4 + T - 1) / T;
    int bN = (NN + T - 1) / T;          // 391
    int bW = (NN * 32 + T - 1) / T;     // 12500 (warp per node, exact)
    int bM = (NN + 127) / 128;          // 782 tiles

    k_fill<<<bE, T>>>(src, dst);
    k_pre<<<bN, T>>>(x, W2);
    k_layer1<<<bN, T>>>(W1, b1);
    k_agg2<<<bW, T>>>();
    k_gemm2pool<<<bM, T, SMEM_MMA>>>(b2, batch, Wl, bl, out);
}

// round 17
// speedup vs baseline: 1.1395x; 1.1395x over previous
#include <cuda_runtime.h>
#include <cuda_fp16.h>

#define NN   100000
#define EE   1600000
#define GG   100
#define HH   128
#define OUTF 10
#define CAP  128
#define PITCH 136   // smem row pitch in halves (conflict-free for ldmatrix)

// ---------- device scratch (static zero-init; self-cleaning across replays) ----------
__device__ __half g_hs1[(size_t)NN * HH];  // dis * relu(layer1)  (pre-scaled msgs)
__device__ __half g_ts[(size_t)NN * HH];   // dis * T  (gemm2 input)
__device__ __half g_W2h[HH * HH];          // W2 in fp16 (built by k_pre)
__device__ int    g_pad[(size_t)NN * CAP]; // scaled src indices (src*32)
__device__ int    g_cur[NN];               // in-degree / cursor (zeroed by k_agg2)
__device__ float4 g_xs[NN];                // (dis*x0, dis*x1, dis*x2, dis)
__device__ float  g_dis[NN];
__device__ float  g_pooled[GG * HH];       // zeroed by k_final
__device__ float  g_gcnt[GG];              // zeroed by k_final

__device__ __forceinline__ unsigned smem_u32(const void* p) {
    return (unsigned)__cvta_generic_to_shared(p);
}
__device__ __forceinline__ uint2 pack_h4(float4 o) {
    __half2 lo = __floats2half2_rn(o.x, o.y);
    __half2 hi = __floats2half2_rn(o.z, o.w);
    uint2 r; r.x = *(unsigned*)&lo; r.y = *(unsigned*)&hi; return r;
}

// ---------- mma / ldmatrix ----------
__device__ __forceinline__ void mma16816(float d[4], const unsigned a[4],
                                         const unsigned b[2], const float c[4]) {
    asm volatile(
        "mma.sync.aligned.m16n8k16.row.col.f32.f16.f16.f32 "
        "{%0,%1,%2,%3}, {%4,%5,%6,%7}, {%8,%9}, {%10,%11,%12,%13};\n"
        : "=f"(d[0]), "=f"(d[1]), "=f"(d[2]), "=f"(d[3])
        : "r"(a[0]), "r"(a[1]), "r"(a[2]), "r"(a[3]),
          "r"(b[0]), "r"(b[1]),
          "f"(c[0]), "f"(c[1]), "f"(c[2]), "f"(c[3]));
}
__device__ __forceinline__ void ldsm_x4(unsigned r[4], unsigned addr) {
    asm volatile("ldmatrix.sync.aligned.m8n8.x4.shared.b16 {%0,%1,%2,%3}, [%4];\n"
        : "=r"(r[0]), "=r"(r[1]), "=r"(r[2]), "=r"(r[3]) : "r"(addr));
}
__device__ __forceinline__ void ldsm_x2_t(unsigned r[2], unsigned addr) {
    asm volatile("ldmatrix.sync.aligned.m8n8.x2.trans.shared.b16 {%0,%1}, [%2];\n"
        : "=r"(r[0]), "=r"(r[1]) : "r"(addr));
}

// ---------- fp16 feature-space gather (lane owns 4 features = uint2) ----------
__device__ __forceinline__ void hacc2(__half2& h0, __half2& h1, uint2 v) {
    h0 = __hadd2(h0, *(__half2*)&v.x);
    h1 = __hadd2(h1, *(__half2*)&v.y);
}

__device__ __forceinline__ float4 gather_sum_h(const __half* __restrict__ buf,
                                               int n, int lane) {
    int cnt = g_cur[n]; if (cnt > CAP) cnt = CAP;
    const int* lst = g_pad + (size_t)n * CAP;
    const uint2* A = (const uint2*)buf;           // row = 32 uint2
    float4 fa = {0.f, 0.f, 0.f, 0.f};
    const __half2 z = __float2half2_rn(0.f);
    __half2 h0 = z, h1 = z;

    int k = 0, sf = 0;
    for (; k + 8 <= cnt; k += 8) {
        int4 a = *(const int4*)&lst[k];
        int4 b = *(const int4*)&lst[k + 4];
        uint2 v0 = __ldg(&A[a.x + lane]);
        uint2 v1 = __ldg(&A[a.y + lane]);
        uint2 v2 = __ldg(&A[a.z + lane]);
        uint2 v3 = __ldg(&A[a.w + lane]);
        uint2 v4 = __ldg(&A[b.x + lane]);
        uint2 v5 = __ldg(&A[b.y + lane]);
        uint2 v6 = __ldg(&A[b.z + lane]);
        uint2 v7 = __ldg(&A[b.w + lane]);
        hacc2(h0, h1, v0); hacc2(h0, h1, v1);
        hacc2(h0, h1, v2); hacc2(h0, h1, v3);
        hacc2(h0, h1, v4); hacc2(h0, h1, v5);
        hacc2(h0, h1, v6); hacc2(h0, h1, v7);
        if (++sf == 2) {                          // flush every 16 edges
            float2 f0 = __half22float2(h0), f1 = __half22float2(h1);
            fa.x += f0.x; fa.y += f0.y; fa.z += f1.x; fa.w += f1.y;
            h0 = z; h1 = z; sf = 0;
        }
    }
    if (k + 4 <= cnt) {
        int4 a = *(const int4*)&lst[k];
        uint2 v0 = __ldg(&A[a.x + lane]);
        uint2 v1 = __ldg(&A[a.y + lane]);
        uint2 v2 = __ldg(&A[a.z + lane]);
        uint2 v3 = __ldg(&A[a.w + lane]);
        hacc2(h0, h1, v0); hacc2(h0, h1, v1);
        hacc2(h0, h1, v2); hacc2(h0, h1, v3);
        k += 4;
    }
    for (; k < cnt; k++)
        hacc2(h0, h1, __ldg(&A[__ldg(&lst[k]) + lane]));
    hacc2(h0, h1, A[n * 32 + lane]);              // self loop (pre-scaled row)
    float2 f0 = __half22float2(h0), f1 = __half22float2(h1);
    fa.x += f0.x; fa.y += f0.y; fa.z += f1.x; fa.w += f1.y;
    return fa;
}

// ---------- kernels ----------
__global__ void k_fill(const int* __restrict__ src, const int* __restrict__ dst) {
    int i = blockIdx.x * blockDim.x + threadIdx.x;
    if (i >= EE / 4) return;
    int4 d4 = __ldg(&((const int4*)dst)[i]);
    int4 s4 = __ldg(&((const int4*)src)[i]);
    int p0 = atomicAdd(&g_cur[d4.x], 1); if (p0 < CAP) g_pad[d4.x * CAP + p0] = s4.x * 32;
    int p1 = atomicAdd(&g_cur[d4.y], 1); if (p1 < CAP) g_pad[d4.y * CAP + p1] = s4.y * 32;
    int p2 = atomicAdd(&g_cur[d4.z], 1); if (p2 < CAP) g_pad[d4.z * CAP + p2] = s4.z * 32;
    int p3 = atomicAdd(&g_cur[d4.w], 1); if (p3 < CAP) g_pad[d4.w * CAP + p3] = s4.w * 32;
}

// dis + pre-scaled x; also converts W2 -> fp16 (threads 0..16383)
__global__ void k_pre(const float* __restrict__ x, const float* __restrict__ W2) {
    int i = blockIdx.x * blockDim.x + threadIdx.x;
    if (i < HH * HH) g_W2h[i] = __float2half_rn(__ldg(&W2[i]));
    if (i >= NN) return;
    float dis = rsqrtf((float)(g_cur[i] + 1));
    g_dis[i] = dis;
    float x0 = __ldg(&x[i * 3 + 0]);
    float x1 = __ldg(&x[i * 3 + 1]);
    float x2 = __ldg(&x[i * 3 + 2]);
    g_xs[i] = make_float4(dis * x0, dis * x1, dis * x2, dis);
}

// Layer 1 fused: x-space gather (thread per node, MLP-8) + W1 gemm
__global__ void __launch_bounds__(256) k_layer1(const float* __restrict__ W1,
                                                const float* __restrict__ b1) {
    __shared__ float4 sS[256];
    int tid = threadIdx.x;
    int n = blockIdx.x * 256 + tid;

    if (n < NN) {
        int cnt = g_cur[n]; if (cnt > CAP) cnt = CAP;
        const int* lst = g_pad + (size_t)n * CAP;
        float4 self = g_xs[n];
        float dis = self.w;
        float sx = self.x, sy = self.y, sz = self.z;
        int k = 0;
        for (; k + 8 <= cnt; k += 8) {
            int4 a = *(const int4*)&lst[k];
            int4 b = *(const int4*)&lst[k + 4];
            float4 v0 = __ldg(&g_xs[a.x >> 5]);
            float4 v1 = __ldg(&g_xs[a.y >> 5]);
            float4 v2 = __ldg(&g_xs[a.z >> 5]);
            float4 v3 = __ldg(&g_xs[a.w >> 5]);
            float4 v4 = __ldg(&g_xs[b.x >> 5]);
            float4 v5 = __ldg(&g_xs[b.y >> 5]);
            float4 v6 = __ldg(&g_xs[b.z >> 5]);
            float4 v7 = __ldg(&g_xs[b.w >> 5]);
            sx += v0.x + v1.x + v2.x + v3.x + v4.x + v5.x + v6.x + v7.x;
            sy += v0.y + v1.y + v2.y + v3.y + v4.y + v5.y + v6.y + v7.y;
            sz += v0.z + v1.z + v2.z + v3.z + v4.z + v5.z + v6.z + v7.z;
        }
        if (k + 4 <= cnt) {
            int4 a = *(const int4*)&lst[k];
            float4 v0 = __ldg(&g_xs[a.x >> 5]);
            float4 v1 = __ldg(&g_xs[a.y >> 5]);
            float4 v2 = __ldg(&g_xs[a.z >> 5]);
            float4 v3 = __ldg(&g_xs[a.w >> 5]);
            sx += v0.x + v1.x + v2.x + v3.x;
            sy += v0.y + v1.y + v2.y + v3.y;
            sz += v0.z + v1.z + v2.z + v3.z;
            k += 4;
        }
        for (; k < cnt; k++) {
            float4 v = __ldg(&g_xs[__ldg(&lst[k]) >> 5]);
            sx += v.x; sy += v.y; sz += v.z;
        }
        sS[tid] = make_float4(sx, sy, sz, dis);
    }
    __syncthreads();

    int w = tid >> 5, lane = tid & 31;
    const float4* W = ((const float4*)W1) + lane;
    float4 w0 = W[0], w1 = W[32], w2 = W[64];
    float4 bb = ((const float4*)b1)[lane];
    int base = blockIdx.x * 256 + w * 32;
#pragma unroll 4
    for (int it = 0; it < 32; it++) {
        int node = base + it;
        if (node >= NN) break;
        float4 s = sS[w * 32 + it];
        float dis = s.w;
        float4 o;
        float tx = fmaf(dis, fmaf(s.x, w0.x, fmaf(s.y, w1.x, s.z * w2.x)), bb.x);
        float ty = fmaf(dis, fmaf(s.x, w0.y, fmaf(s.y, w1.y, s.z * w2.y)), bb.y);
        float tz = fmaf(dis, fmaf(s.x, w0.z, fmaf(s.y, w1.z, s.z * w2.z)), bb.z);
        float tw = fmaf(dis, fmaf(s.x, w0.w, fmaf(s.y, w1.w, s.z * w2.w)), bb.w);
        o.x = fmaxf(tx, 0.f) * dis;
        o.y = fmaxf(ty, 0.f) * dis;
        o.z = fmaxf(tz, 0.f) * dis;
        o.w = fmaxf(tw, 0.f) * dis;
        ((uint2*)(g_hs1 + (size_t)node * HH))[lane] = pack_h4(o);
    }
}

// Layer-2 gather: ts = dis_i * (hs1_i + sum_j hs1_j). Warp per node (high occ).
__global__ void __launch_bounds__(256) k_agg2() {
    int gid = blockIdx.x * blockDim.x + threadIdx.x;
    int n = gid >> 5, lane = gid & 31;
    float4 a = gather_sum_h(g_hs1, n, lane);
    if (lane == 0) g_cur[n] = 0;               // self-clean for next launch
    float dis = g_dis[n];
    float4 o;
    o.x = a.x * dis; o.y = a.y * dis; o.z = a.z * dis; o.w = a.w * dis;
    ((uint2*)(g_ts + (size_t)n * HH))[lane] = pack_h4(o);
}

// HMMA ts@W2 + bias + relu + mean-pool (W2 staged from precomputed fp16).
__global__ void __launch_bounds__(256) k_gemm2pool(const float* __restrict__ b2,
                                                   const int* __restrict__ batch) {
    extern __shared__ __half sh[];
    __half* sh_h = sh;                  // [128][PITCH]
    __half* sh_w = sh + 128 * PITCH;    // [128][PITCH]
    __shared__ float sb2[HH];
    __shared__ int sbatch[128];
    int t = threadIdx.x;
    int nb0 = blockIdx.x * 128;

    for (int i = t; i < 128 * 16; i += 256) {
        int r = i >> 4, c8 = (i & 15) * 8;
        int node = nb0 + r; if (node >= NN) node = NN - 1;
        *(uint4*)&sh_h[r * PITCH + c8] = *(const uint4*)&g_ts[(size_t)node * HH + c8];
        *(uint4*)&sh_w[r * PITCH + c8] = *(const uint4*)&g_W2h[r * HH + c8];
    }
    if (t < HH) sb2[t] = __ldg(&b2[t]);
    if (t < 128) {
        int node = nb0 + t;
        sbatch[t] = (node < NN) ? __ldg(&batch[node]) : -1;
    }
    __syncthreads();

    int w = t >> 5, lane = t & 31;
    int r0 = w * 16;
    float acc[16][4];
#pragma unroll
    for (int j = 0; j < 16; j++)
#pragma unroll
        for (int q = 0; q < 4; q++) acc[j][q] = 0.f;

    int a_row = r0 + (lane & 15);
    int a_col = (lane >> 4) * 8;
    int b_lane = lane & 15;

    for (int kc = 0; kc < 8; kc++) {
        int k0 = kc * 16;
        unsigned a[4];
        ldsm_x4(a, smem_u32(&sh_h[a_row * PITCH + k0 + a_col]));
        unsigned b_base = smem_u32(&sh_w[(k0 + b_lane) * PITCH]);
#pragma unroll
        for (int j = 0; j < 16; j++) {
            unsigned b[2];
            ldsm_x2_t(b, b_base + j * 8 * sizeof(__half));
            mma16816(acc[j], a, b, acc[j]);
        }
    }
    __syncthreads();                    // reuse smem as fp32 staging

    float* stg = (float*)sh;            // [128][128] fp32 = 64KB
    int lrow = lane >> 2;
    int lcol = (lane & 3) * 2;
    int row0 = r0 + lrow, row1 = row0 + 8;
#pragma unroll
    for (int j = 0; j < 16; j++) {
        int col = j * 8 + lcol;
        stg[row0 * 128 + col]     = fmaxf(acc[j][0] + sb2[col], 0.f);
        stg[row0 * 128 + col + 1] = fmaxf(acc[j][1] + sb2[col + 1], 0.f);
        stg[row1 * 128 + col]     = fmaxf(acc[j][2] + sb2[col], 0.f);
        stg[row1 * 128 + col + 1] = fmaxf(acc[j][3] + sb2[col + 1], 0.f);
    }
    __syncthreads();

    if (t < HH) {
        int g0 = sbatch[0];
        float s = 0.f;
        for (int r = 0; r < 128; r++) {
            int g = sbatch[r];
            if (g < 0) continue;
            float v = stg[r * 128 + t];
            if (g == g0) s += v;
            else atomicAdd(&g_pooled[g * HH + t], v);
        }
        atomicAdd(&g_pooled[g0 * HH + t], s);
    } else if (t == HH) {
        int g0 = sbatch[0];
        float c0 = 0.f;
        for (int r = 0; r < 128; r++) {
            int g = sbatch[r];
            if (g < 0) continue;
            if (g == g0) c0 += 1.f;
            else atomicAdd(&g_gcnt[g], 1.f);
        }
        atomicAdd(&g_gcnt[g0], c0);
    }
}

// final head (single block) + zero pooled state for next replay
__global__ void __launch_bounds__(1024) k_final(const float* __restrict__ Wl,
                                                const float* __restrict__ bl,
                                                float* __restrict__ out) {
    int idx = threadIdx.x;
    if (idx < GG * OUTF) {
        int g = idx / OUTF, o = idx % OUTF;
        float inv = 1.f / fmaxf(g_gcnt[g], 1.f);
        float s = 0.f;
#pragma unroll 8
        for (int k = 0; k < HH; k++)
            s = fmaf(g_pooled[g * HH + k], Wl[k * OUTF + o], s);
        out[idx] = fmaf(s, inv, bl[o]);
    }
    __syncthreads();
    for (int i = idx; i < GG * HH; i += 1024) g_pooled[i] = 0.f;
    if (idx < GG) g_gcnt[idx] = 0.f;
}

// ---------- launch ----------
extern "C" void kernel_launch(void* const* d_in, const int* in_sizes, int n_in,
                              void* d_out, int out_size) {
    const float* x     = (const float*)d_in[0];
    const int*   ei    = (const int*)d_in[1];
    const int*   src   = ei;
    const int*   dst   = ei + EE;
    const int*   batch = (const int*)d_in[2];
    const float* W1    = (const float*)d_in[3];
    const float* b1    = (const float*)d_in[4];
    const float* W2    = (const float*)d_in[5];
    const float* b2    = (const float*)d_in[6];
    const float* Wl    = (const float*)d_in[7];
    const float* bl    = (const float*)d_in[8];
    float* out = (float*)d_out;

    const int SMEM_MMA = 2 * 128 * PITCH * (int)sizeof(__half);   // 69632
    cudaFuncSetAttribute(k_gemm2pool,
                         cudaFuncAttributeMaxDynamicSharedMemorySize, SMEM_MMA);

    const int T = 256;
    int bE = (EE / 4 + T - 1) / T;
    int bN = (NN + T - 1) / T;          // 391
    int bW = (NN * 32 + T - 1) / T;     // 12500 (warp per node, exact)
    int bM = (NN + 127) / 128;          // 782 tiles

    k_fill<<<bE, T>>>(src, dst);
    k_pre<<<bN, T>>>(x, W2);
    k_layer1<<<bN, T>>>(W1, b1);
    k_agg2<<<bW, T>>>();
    k_gemm2pool<<<bM, T, SMEM_MMA>>>(b2, batch);
    k_final<<<1, 1024>>>(Wl, bl, out);
}